// round 6
// baseline (speedup 1.0000x reference)
#include <cuda_runtime.h>
#include <cuda_bf16.h>
#include <cstdint>

// ---------------- problem constants ----------------
#define NB 64
#define NS 1024
#define NH 512
#define NM (NB*NS)          // 65536 rows
#define PLANE ((size_t)NM*NH)

// GEMM tiling: BM=BN=128, 4 warps (2x2), warp tile 64x64
#define BM 128
#define BN 128
#define BK 32
#define ROWE 40             // padded row length (elems); 80 bytes
#define ROWB 80
#define A_SLOT (BM*ROWB)    // 10240
#define B_SLOT (BN*ROWB)    // 10240
#define SLOT (A_SLOT+B_SLOT)
#define SMEM_BYTES (4*SLOT) // 81920 -> 2 CTAs/SM

// ---------------- device scratch ----------------
__device__ __nv_bfloat16 g_x_hi [PLANE];   // split of `input`
__device__ __nv_bfloat16 g_x_lo [PLANE];
__device__ __nv_bfloat16 g_rh_hi[PLANE];   // r*h
__device__ __nv_bfloat16 g_rh_lo[PLANE];
__device__ __nv_bfloat16 g_h_hi [3*PLANE]; // h outputs per layer
__device__ __nv_bfloat16 g_h_lo [3*PLANE];
__device__ float         g_zp   [PLANE];   // z gate (fp32)
__device__ __nv_bfloat16 g_wzr_hi[(size_t)3*1024*512]; // [z|r] weights^T per layer
__device__ __nv_bfloat16 g_wzr_lo[(size_t)3*1024*512];
__device__ __nv_bfloat16 g_wg_hi [(size_t)3*512*1024]; // [Wgx;Wgh]^T per layer (row stride 1024)
__device__ __nv_bfloat16 g_wg_lo [(size_t)3*512*1024];
__device__ __nv_bfloat16 g_wo_hi [(size_t)512*512];
__device__ __nv_bfloat16 g_wo_lo [(size_t)512*512];
__device__ float g_hz [NB*NH];
__device__ float g_hr [NB*NH];
__device__ float g_h0c[NB*NH];

// ---------------- helpers ----------------
__device__ __forceinline__ uint32_t smem_u32(const void* p) {
    uint32_t a;
    asm("{ .reg .u64 t; cvta.to.shared.u64 t, %1; cvt.u32.u64 %0, t; }" : "=r"(a) : "l"(p));
    return a;
}
__device__ __forceinline__ void cp_async16(uint32_t dst, const void* src) {
    asm volatile("cp.async.cg.shared.global [%0], [%1], 16;" :: "r"(dst), "l"(src) : "memory");
}
__device__ __forceinline__ void cp_commit() { asm volatile("cp.async.commit_group;" ::: "memory"); }
__device__ __forceinline__ void cp_wait2()  { asm volatile("cp.async.wait_group 2;" ::: "memory"); }
__device__ __forceinline__ void ldmatrix4(uint32_t& r0, uint32_t& r1, uint32_t& r2, uint32_t& r3, uint32_t addr) {
    asm volatile("ldmatrix.sync.aligned.m8n8.x4.shared.b16 {%0,%1,%2,%3}, [%4];"
                 : "=r"(r0), "=r"(r1), "=r"(r2), "=r"(r3) : "r"(addr));
}
__device__ __forceinline__ void mma_bf16(float* d, const uint32_t* a, const uint32_t* b) {
    asm volatile("mma.sync.aligned.m16n8k16.row.col.f32.bf16.bf16.f32 "
        "{%0,%1,%2,%3}, {%4,%5,%6,%7}, {%8,%9}, {%0,%1,%2,%3};"
        : "+f"(d[0]), "+f"(d[1]), "+f"(d[2]), "+f"(d[3])
        : "r"(a[0]), "r"(a[1]), "r"(a[2]), "r"(a[3]), "r"(b[0]), "r"(b[1]));
}
__device__ __forceinline__ void split2(float v, __nv_bfloat16& hi, __nv_bfloat16& lo) {
    hi = __float2bfloat16(v);
    lo = __float2bfloat16(v - __bfloat162float(hi));
}

// ---------------- prep kernels ----------------
__global__ void k_split(const float4* __restrict__ x,
                        __nv_bfloat16* __restrict__ hi, __nv_bfloat16* __restrict__ lo) {
    size_t i = (size_t)blockIdx.x * blockDim.x + threadIdx.x;
    float4 v = x[i];
    float a[4] = {v.x, v.y, v.z, v.w};
    #pragma unroll
    for (int j = 0; j < 4; j++) {
        __nv_bfloat16 h, l; split2(a[j], h, l);
        hi[4*i + j] = h; lo[4*i + j] = l;
    }
}

// All 13 weight-prep jobs in one launch: transpose + optional add + split.
// job j<12: layer l=j/4, sub=j%4 (0:z 1:r 2:gx 3:gh); j==12: Wout.
__global__ void k_wprep_all(
    const float* __restrict__ Wzx, const float* __restrict__ Wzh,
    const float* __restrict__ Wrx, const float* __restrict__ Wrh,
    const float* __restrict__ Wgx, const float* __restrict__ Wgh,
    const float* __restrict__ Wout,
    __nv_bfloat16* __restrict__ wzrH, __nv_bfloat16* __restrict__ wzrL,
    __nv_bfloat16* __restrict__ wgH,  __nv_bfloat16* __restrict__ wgL,
    __nv_bfloat16* __restrict__ woH,  __nv_bfloat16* __restrict__ woL)
{
    const int j = blockIdx.z;
    const size_t WS = (size_t)512*512;
    const float *W, *W2 = nullptr;
    __nv_bfloat16 *hi, *lo;
    int dstride;
    if (j == 12) {
        W = Wout; hi = woH; lo = woL; dstride = 512;
    } else {
        int l = j >> 2, s = j & 3;
        size_t zroff = (size_t)l*1024*512, goff = (size_t)l*512*1024;
        if (s == 0) { W = Wzx + l*WS; W2 = l ? Wzh + l*WS : nullptr;
                      hi = wzrH + zroff; lo = wzrL + zroff; dstride = 512; }
        else if (s == 1) { W = Wrx + l*WS; W2 = l ? Wrh + l*WS : nullptr;
                      hi = wzrH + zroff + WS; lo = wzrL + zroff + WS; dstride = 512; }
        else if (s == 2) { W = Wgx + l*WS; hi = wgH + goff; lo = wgL + goff; dstride = 1024; }
        else { W = Wgh + l*WS; hi = wgH + goff + 512; lo = wgL + goff + 512; dstride = 1024; }
    }
    __shared__ float t[32][33];
    int k0 = blockIdx.y * 32, n0 = blockIdx.x * 32;
    for (int r = threadIdx.y; r < 32; r += 8) {
        float v = W[(size_t)(k0 + r) * 512 + n0 + threadIdx.x];
        if (W2) v += W2[(size_t)(k0 + r) * 512 + n0 + threadIdx.x];
        t[r][threadIdx.x] = v;
    }
    __syncthreads();
    for (int r = threadIdx.y; r < 32; r += 8) {
        float v = t[threadIdx.x][r];
        __nv_bfloat16 h, l; split2(v, h, l);
        hi[(size_t)(n0 + r) * dstride + k0 + threadIdx.x] = h;
        lo[(size_t)(n0 + r) * dstride + k0 + threadIdx.x] = l;
    }
}

__global__ void k_pre(const float* __restrict__ hs,
                      const float* __restrict__ Wzh0, const float* __restrict__ Wrh0,
                      float* __restrict__ hz, float* __restrict__ hr, float* __restrict__ h0c) {
    __shared__ float h0s[512];
    int b = blockIdx.x, n = threadIdx.x;
    float h0v = hs[b*3*NH + n];
    h0s[n] = h0v;
    if (blockIdx.y == 0) h0c[b*NH + n] = h0v;
    __syncthreads();
    const float* W = blockIdx.y ? Wrh0 : Wzh0;
    float acc = 0.f;
    #pragma unroll 8
    for (int k = 0; k < 512; k++) acc = fmaf(h0s[k], W[k*512 + n], acc);
    (blockIdx.y ? hr : hz)[b*NH + n] = acc;
}

__global__ void k_tail(const float* __restrict__ hs,
                       const __nv_bfloat16* __restrict__ h0hi, const __nv_bfloat16* __restrict__ h0lo,
                       const __nv_bfloat16* __restrict__ h1hi, const __nv_bfloat16* __restrict__ h1lo,
                       float* __restrict__ out_h) {
    int b = blockIdx.x, n = threadIdx.x;
    size_t last = ((size_t)b*NS + (NS-1)) * (size_t)NH + n;
    out_h[b*3*NH + n]        = hs[b*3*NH + n];
    out_h[b*3*NH + 512 + n]  = __bfloat162float(h0hi[last]) + __bfloat162float(h0lo[last]);
    out_h[b*3*NH + 1024 + n] = __bfloat162float(h1hi[last]) + __bfloat162float(h1lo[last]);
}

// ---------------- fused bf16x3 HMMA GEMM ----------------
// 128 threads, 4 warps (2x2), warp tile 64x64.
// MODE 0 (G1): N=1024 ([z|r]), K'=1536. cols<512: z=sigmoid(acc+bz+hz) -> fp32 plane
//              cols>=512: r=sigmoid(acc+br+hr); rh = r*hv -> bf16 hi/lo
// MODE 1 (G2): N=512, K'=3072 over [x|rh]@[Wgx;Wgh]. g=tanh(acc+bg);
//              h' = z*hv + (1-z)*g -> bf16 hi/lo
// MODE 2 (OUT): N=512, K'=1536, Cf = acc + bo
struct GP {
    const __nv_bfloat16 *Ahi, *Alo;
    const __nv_bfloat16 *A2hi, *A2lo;    // rh planes (MODE 1)
    const __nv_bfloat16 *Bhi, *Blo;
    float* zout;
    __nv_bfloat16 *rhhi, *rhlo;
    const float *bz, *br;
    const float *hz, *hr;
    const float* h0c;
    const __nv_bfloat16 *hvhi, *hvlo;
    const float* zin;
    const float* bg;
    __nv_bfloat16 *Chi, *Clo;
    float* Cf; const float* bo;
};

template<int MODE>
__global__ void __launch_bounds__(128, 2) gemm_f(const GP p) {
    constexpr int ITERS = (MODE == 1) ? 96 : 48;
    constexpr int BSTR  = (MODE == 1) ? 1024 : 512;
    extern __shared__ char smem_raw[];
    const uint32_t base = smem_u32(smem_raw);
    const int tid = threadIdx.x;
    const int lane = tid & 31;
    const int w = tid >> 5;
    const int wr = w >> 1;          // 0..1 (64 rows)
    const int wc = w & 1;           // 0..1 (64 cols)
    const int bm = blockIdx.y * BM;
    const int bn = blockIdx.x * BN;

    float c[4][8][4];
    #pragma unroll
    for (int i = 0; i < 4; i++)
        #pragma unroll
        for (int j = 0; j < 8; j++)
            #pragma unroll
            for (int e = 0; e < 4; e++) c[i][j][e] = 0.f;

    const uint32_t a_lm = ((wr*64 + ((lane>>3)&1)*8 + (lane&7)) * ROWE + (lane>>4)*8) * 2;
    const uint32_t b_lm = ((wc*64 + (lane>>4)*8 + (lane&7)) * ROWE + ((lane>>3)&1)*8) * 2;

    auto issue = [&](int cidx) {
        const __nv_bfloat16 *ap, *bp;
        int acol, bcol;
        if (MODE == 1) {
            int seg = cidx >> 5, kk = (cidx & 31) << 5;
            bool sec = kk >= 512;
            const __nv_bfloat16* axh = sec ? p.A2hi : p.Ahi;
            const __nv_bfloat16* axl = sec ? p.A2lo : p.Alo;
            ap = (seg == 2) ? axl : axh;
            bp = (seg == 1) ? p.Blo : p.Bhi;
            acol = kk & 511; bcol = kk;
        } else {
            int seg = cidx >> 4, kk = (cidx & 15) << 5;
            ap = (seg == 2) ? p.Alo : p.Ahi;
            bp = (seg == 1) ? p.Blo : p.Bhi;
            acol = kk; bcol = kk;
        }
        const int slot = cidx & 3;
        const uint32_t sA = base + slot * SLOT;
        const uint32_t sB = sA + A_SLOT;
        #pragma unroll
        for (int i = 0; i < 4; i++) {
            int ch = tid + i * 128;
            int row = ch >> 2, cs = ch & 3;
            cp_async16(sA + row * ROWB + cs * 16,
                       ap + (size_t)(bm + row) * 512 + acol + cs * 8);
        }
        #pragma unroll
        for (int i = 0; i < 4; i++) {
            int ch = tid + i * 128;
            int row = ch >> 2, cs = ch & 3;
            cp_async16(sB + row * ROWB + cs * 16,
                       bp + (size_t)(bn + row) * BSTR + bcol + cs * 8);
        }
    };

    issue(0); cp_commit();
    issue(1); cp_commit();
    issue(2); cp_commit();

    for (int it = 0; it < ITERS; it++) {
        cp_wait2();
        __syncthreads();
        if (it + 3 < ITERS) issue(it + 3);
        cp_commit();

        const int slot = it & 3;
        const uint32_t sA = base + slot * SLOT;
        const uint32_t sB = sA + A_SLOT;
        #pragma unroll
        for (int kh = 0; kh < 2; kh++) {
            const uint32_t koffB = kh * 32;
            uint32_t a[4][4], b[8][2];
            #pragma unroll
            for (int mt = 0; mt < 4; mt++)
                ldmatrix4(a[mt][0], a[mt][1], a[mt][2], a[mt][3],
                          sA + a_lm + mt * (16*ROWB) + koffB);
            #pragma unroll
            for (int np = 0; np < 4; np++) {
                uint32_t r0, r1, r2, r3;
                ldmatrix4(r0, r1, r2, r3, sB + b_lm + np * (16*ROWB) + koffB);
                b[np*2][0] = r0;   b[np*2][1] = r1;
                b[np*2+1][0] = r2; b[np*2+1][1] = r3;
            }
            #pragma unroll
            for (int mt = 0; mt < 4; mt++)
                #pragma unroll
                for (int nt = 0; nt < 8; nt++)
                    mma_bf16(c[mt][nt], a[mt], b[nt]);
        }
    }

    // ---- fused epilogue ----
    const int rbase = bm + wr * 64;
    const int cbase = bn + wc * 64;
    const int gate = (MODE == 0) ? (bn >> 9) : 0;   // uniform per CTA (BN=128)
    #pragma unroll
    for (int mt = 0; mt < 4; mt++) {
        #pragma unroll
        for (int er = 0; er < 2; er++) {
            const int gm = rbase + mt*16 + (lane >> 2) + er*8;
            const int bb = gm >> 10;
            #pragma unroll
            for (int nt = 0; nt < 8; nt++) {
                #pragma unroll
                for (int ec = 0; ec < 2; ec++) {
                    const int gn = cbase + nt*8 + (lane & 3)*2 + ec;
                    float v = c[mt][nt][er*2 + ec];
                    if (MODE == 0) {
                        const int gnn = gn & 511;
                        const size_t idx = (size_t)gm * NH + gnn;
                        v += (gate ? p.br : p.bz)[gnn];
                        if (p.hz) v += (gate ? p.hr : p.hz)[bb * NH + gnn];
                        float s = 1.f / (1.f + __expf(-v));
                        if (!gate) {
                            p.zout[idx] = s;
                        } else {
                            float hv = p.h0c ? p.h0c[bb * NH + gnn]
                                : __bfloat162float(p.hvhi[idx]) + __bfloat162float(p.hvlo[idx]);
                            float o = s * hv;
                            __nv_bfloat16 h, l; split2(o, h, l);
                            p.rhhi[idx] = h; p.rhlo[idx] = l;
                        }
                    } else if (MODE == 1) {
                        const size_t idx = (size_t)gm * NH + gn;
                        float g = tanhf(v + p.bg[gn]);
                        float z = p.zin[idx];
                        float hv = p.h0c ? p.h0c[bb * NH + gn]
                            : __bfloat162float(p.hvhi[idx]) + __bfloat162float(p.hvlo[idx]);
                        float o = z * hv + (1.f - z) * g;
                        __nv_bfloat16 h, l; split2(o, h, l);
                        p.Chi[idx] = h; p.Clo[idx] = l;
                    } else {
                        p.Cf[(size_t)gm * NH + gn] = v + p.bo[gn];
                    }
                }
            }
        }
    }
}

// ---------------- host ----------------
extern "C" void kernel_launch(void* const* d_in, const int* in_sizes, int n_in,
                              void* d_out, int out_size) {
    const float* input = (const float*)d_in[0];
    const float* hs    = (const float*)d_in[1];
    const float* Wzx   = (const float*)d_in[2];
    const float* bzx   = (const float*)d_in[3];
    const float* Wzh   = (const float*)d_in[4];
    const float* Wrx   = (const float*)d_in[5];
    const float* brx   = (const float*)d_in[6];
    const float* Wrh   = (const float*)d_in[7];
    const float* Wgx   = (const float*)d_in[8];
    const float* bgx   = (const float*)d_in[9];
    const float* Wgh   = (const float*)d_in[10];
    const float* Wout  = (const float*)d_in[11];
    const float* bout  = (const float*)d_in[12];
    float* out = (float*)d_out;

    __nv_bfloat16 *xhi, *xlo, *rhhi, *rhlo, *hhi, *hlo;
    __nv_bfloat16 *wzrH, *wzrL, *wgH, *wgL, *woH, *woL;
    float *zp, *hz, *hr, *h0c;
    cudaGetSymbolAddress((void**)&xhi,  g_x_hi);
    cudaGetSymbolAddress((void**)&xlo,  g_x_lo);
    cudaGetSymbolAddress((void**)&rhhi, g_rh_hi);
    cudaGetSymbolAddress((void**)&rhlo, g_rh_lo);
    cudaGetSymbolAddress((void**)&hhi,  g_h_hi);
    cudaGetSymbolAddress((void**)&hlo,  g_h_lo);
    cudaGetSymbolAddress((void**)&zp,   g_zp);
    cudaGetSymbolAddress((void**)&wzrH, g_wzr_hi);
    cudaGetSymbolAddress((void**)&wzrL, g_wzr_lo);
    cudaGetSymbolAddress((void**)&wgH,  g_wg_hi);
    cudaGetSymbolAddress((void**)&wgL,  g_wg_lo);
    cudaGetSymbolAddress((void**)&woH,  g_wo_hi);
    cudaGetSymbolAddress((void**)&woL,  g_wo_lo);
    cudaGetSymbolAddress((void**)&hz,   g_hz);
    cudaGetSymbolAddress((void**)&hr,   g_hr);
    cudaGetSymbolAddress((void**)&h0c,  g_h0c);

    cudaFuncSetAttribute(gemm_f<0>, cudaFuncAttributeMaxDynamicSharedMemorySize, SMEM_BYTES);
    cudaFuncSetAttribute(gemm_f<1>, cudaFuncAttributeMaxDynamicSharedMemorySize, SMEM_BYTES);
    cudaFuncSetAttribute(gemm_f<2>, cudaFuncAttributeMaxDynamicSharedMemorySize, SMEM_BYTES);

    // ---- prep (3 launches) ----
    k_split<<<PLANE/4/256, 256>>>((const float4*)input, xhi, xlo);
    k_pre<<<dim3(64,2), 512>>>(hs, Wzh, Wrh, hz, hr, h0c);
    k_wprep_all<<<dim3(16,16,13), dim3(32,8)>>>(Wzx, Wzh, Wrx, Wrh, Wgx, Wgh, Wout,
                                                wzrH, wzrL, wgH, wgL, woH, woL);

    const dim3 g1(8, 512), g2(4, 512), blk(128);

    for (int l = 0; l < 3; l++) {
        const __nv_bfloat16* XH = l ? (hhi + (size_t)(l-1)*PLANE) : xhi;
        const __nv_bfloat16* XL = l ? (hlo + (size_t)(l-1)*PLANE) : xlo;
        GP p{};
        // ---- G1: [z|r] gates ----
        p.Ahi = XH; p.Alo = XL;
        p.Bhi = wzrH + (size_t)l*1024*512; p.Blo = wzrL + (size_t)l*1024*512;
        p.zout = zp; p.rhhi = rhhi; p.rhlo = rhlo;
        p.bz = bzx + l*512; p.br = brx + l*512;
        p.hz = l ? nullptr : hz; p.hr = l ? nullptr : hr;
        p.h0c = l ? nullptr : h0c;
        p.hvhi = XH; p.hvlo = XL;
        gemm_f<0><<<g1, blk, SMEM_BYTES>>>(p);
        // ---- G2: g gate + combine ----
        GP q{};
        q.Ahi = XH; q.Alo = XL; q.A2hi = rhhi; q.A2lo = rhlo;
        q.Bhi = wgH + (size_t)l*512*1024; q.Blo = wgL + (size_t)l*512*1024;
        q.zin = zp; q.bg = bgx + l*512;
        q.h0c = l ? nullptr : h0c;
        q.hvhi = XH; q.hvlo = XL;
        q.Chi = hhi + (size_t)l*PLANE; q.Clo = hlo + (size_t)l*PLANE;
        gemm_f<1><<<g2, blk, SMEM_BYTES>>>(q);
    }
    // ---- output projection ----
    GP o{};
    o.Ahi = hhi + 2*PLANE; o.Alo = hlo + 2*PLANE;
    o.Bhi = woH; o.Blo = woL;
    o.Cf = out; o.bo = bout;
    gemm_f<2><<<g2, blk, SMEM_BYTES>>>(o);

    k_tail<<<64, 512>>>(hs, hhi, hlo, hhi + PLANE, hlo + PLANE, out + PLANE);
}

// round 8
// speedup vs baseline: 1.3932x; 1.3932x over previous
#include <cuda_runtime.h>
#include <cuda_bf16.h>
#include <cstdint>

// ---------------- problem constants ----------------
#define NB 64
#define NS 1024
#define NH 512
#define NM (NB*NS)          // 65536 rows
#define NN 512
#define WSTRIDE (512*512)
#define PLANE ((size_t)NM*NN)

// GEMM tiling: BM=BN=128, 8 warps (2x4), warp tile 64x32.
// Super-iteration: one K=32 chunk, 4 tiles (Ahi,Alo,Bhi,Blo), 96 mmas per warp pair set.
#define BM 128
#define BN 128
#define BK 32
#define NSUP 16             // 512 / 32
#define ROWB 80             // 64B data + 16B pad: 16B-aligned rows, conflict-free (R3-proven)
#define TILE_B (128*ROWB)   // 10240
#define SLOT (4*TILE_B)     // 40960
#define SMEM_BYTES (2*SLOT) // 81920 -> 2 CTAs/SM

#define A_HI_OFF 0
#define A_LO_OFF TILE_B
#define B_HI_OFF (2*TILE_B)
#define B_LO_OFF (3*TILE_B)

// ---------------- device scratch ----------------
__device__ __nv_bfloat16 g_act_hi[(size_t)5*NM*NN];  // 0=X 1=rh 2=h0 3=h1 4=h2
__device__ __nv_bfloat16 g_act_lo[(size_t)5*NM*NN];
__device__ __nv_bfloat16 g_wt_hi[(size_t)13*WSTRIDE]; // B^T [N,K] per slot
__device__ __nv_bfloat16 g_wt_lo[(size_t)13*WSTRIDE];
__device__ float g_z [PLANE];
__device__ float g_ag[PLANE];
__device__ float g_hz [NB*NH];
__device__ float g_hr [NB*NH];
__device__ float g_h0c[NB*NH];

// ---------------- helpers ----------------
__device__ __forceinline__ uint32_t smem_u32(const void* p) {
    uint32_t a;
    asm("{ .reg .u64 t; cvta.to.shared.u64 t, %1; cvt.u32.u64 %0, t; }" : "=r"(a) : "l"(p));
    return a;
}
__device__ __forceinline__ void cp_async16(uint32_t dst, const void* src) {
    asm volatile("cp.async.cg.shared.global [%0], [%1], 16;" :: "r"(dst), "l"(src) : "memory");
}
__device__ __forceinline__ void cp_commit() { asm volatile("cp.async.commit_group;" ::: "memory"); }
__device__ __forceinline__ void cp_wait0()  { asm volatile("cp.async.wait_group 0;" ::: "memory"); }
__device__ __forceinline__ void cp_wait1()  { asm volatile("cp.async.wait_group 1;" ::: "memory"); }
__device__ __forceinline__ void ldmatrix4(uint32_t& r0, uint32_t& r1, uint32_t& r2, uint32_t& r3, uint32_t addr) {
    asm volatile("ldmatrix.sync.aligned.m8n8.x4.shared.b16 {%0,%1,%2,%3}, [%4];"
                 : "=r"(r0), "=r"(r1), "=r"(r2), "=r"(r3) : "r"(addr));
}
__device__ __forceinline__ void mma_bf16(float* d, const uint32_t* a, const uint32_t* b) {
    asm volatile("mma.sync.aligned.m16n8k16.row.col.f32.bf16.bf16.f32 "
        "{%0,%1,%2,%3}, {%4,%5,%6,%7}, {%8,%9}, {%0,%1,%2,%3};"
        : "+f"(d[0]), "+f"(d[1]), "+f"(d[2]), "+f"(d[3])
        : "r"(a[0]), "r"(a[1]), "r"(a[2]), "r"(a[3]), "r"(b[0]), "r"(b[1]));
}
__device__ __forceinline__ void split2(float v, __nv_bfloat16& hi, __nv_bfloat16& lo) {
    hi = __float2bfloat16(v);
    lo = __float2bfloat16(v - __bfloat162float(hi));
}

// ---------------- prep kernels ----------------
__global__ void k_split(const float4* __restrict__ x,
                        __nv_bfloat16* __restrict__ hi, __nv_bfloat16* __restrict__ lo) {
    size_t i = (size_t)blockIdx.x * blockDim.x + threadIdx.x;
    float4 v = x[i];
    float a[4] = {v.x, v.y, v.z, v.w};
    #pragma unroll
    for (int j = 0; j < 4; j++) {
        __nv_bfloat16 h, l; split2(a[j], h, l);
        hi[4*i + j] = h; lo[4*i + j] = l;
    }
}

// All 13 weight-prep jobs in one launch.
// j<12: l=j/4, s=j%4 (0:z 1:r 2:gx 3:gh); z/r fold in h-weights for l>=1. j==12: Wout.
__global__ void k_wprep_all(
    const float* __restrict__ Wzx, const float* __restrict__ Wzh,
    const float* __restrict__ Wrx, const float* __restrict__ Wrh,
    const float* __restrict__ Wgx, const float* __restrict__ Wgh,
    const float* __restrict__ Wout,
    __nv_bfloat16* __restrict__ whi, __nv_bfloat16* __restrict__ wlo)
{
    const int j = blockIdx.z;
    const size_t WS = (size_t)WSTRIDE;
    const float *W, *W2 = nullptr;
    if (j == 12) {
        W = Wout;
    } else {
        int l = j >> 2, s = j & 3;
        if (s == 0)      { W = Wzx + l*WS; W2 = l ? (Wzh + l*WS) : nullptr; }
        else if (s == 1) { W = Wrx + l*WS; W2 = l ? (Wrh + l*WS) : nullptr; }
        else if (s == 2) { W = Wgx + l*WS; }
        else             { W = Wgh + l*WS; }
    }
    __nv_bfloat16* hi = whi + (size_t)j * WS;
    __nv_bfloat16* lo = wlo + (size_t)j * WS;
    __shared__ float t[32][33];
    int k0 = blockIdx.y * 32, n0 = blockIdx.x * 32;
    for (int r = threadIdx.y; r < 32; r += 8) {
        float v = W[(size_t)(k0 + r) * 512 + n0 + threadIdx.x];
        if (W2) v += W2[(size_t)(k0 + r) * 512 + n0 + threadIdx.x];
        t[r][threadIdx.x] = v;
    }
    __syncthreads();
    for (int r = threadIdx.y; r < 32; r += 8) {
        float v = t[threadIdx.x][r];
        __nv_bfloat16 h, l; split2(v, h, l);
        hi[(size_t)(n0 + r) * 512 + k0 + threadIdx.x] = h;
        lo[(size_t)(n0 + r) * 512 + k0 + threadIdx.x] = l;
    }
}

__global__ void k_pre(const float* __restrict__ hs,
                      const float* __restrict__ Wzh0, const float* __restrict__ Wrh0,
                      float* __restrict__ hz, float* __restrict__ hr, float* __restrict__ h0c) {
    __shared__ float h0s[512];
    int b = blockIdx.x, n = threadIdx.x;
    float h0v = hs[b*3*NH + n];
    h0s[n] = h0v;
    if (blockIdx.y == 0) h0c[b*NH + n] = h0v;
    __syncthreads();
    const float* W = blockIdx.y ? Wrh0 : Wzh0;
    float acc = 0.f;
    #pragma unroll 8
    for (int k = 0; k < 512; k++) acc = fmaf(h0s[k], W[k*512 + n], acc);
    (blockIdx.y ? hr : hz)[b*NH + n] = acc;
}

__global__ void k_tail(const float* __restrict__ hs,
                       const __nv_bfloat16* __restrict__ h0hi, const __nv_bfloat16* __restrict__ h0lo,
                       const __nv_bfloat16* __restrict__ h1hi, const __nv_bfloat16* __restrict__ h1lo,
                       float* __restrict__ out_h) {
    int b = blockIdx.x, n = threadIdx.x;
    size_t last = ((size_t)b*NS + (NS-1)) * (size_t)NN + n;
    out_h[b*3*NH + n]        = hs[b*3*NH + n];
    out_h[b*3*NH + 512 + n]  = __bfloat162float(h0hi[last]) + __bfloat162float(h0lo[last]);
    out_h[b*3*NH + 1024 + n] = __bfloat162float(h1hi[last]) + __bfloat162float(h1lo[last]);
}

// ---------------- bf16x3 HMMA GEMM, shared-operand super-iterations ----------------
// C = Ahi@Bhi^T + Ahi@Blo^T + Alo@Bhi^T, K=512, 16 super-iters of K=32.
// EPI 1: z = sigmoid(acc + bias + hterm[b])            -> Cf
// EPI 2: r = sigmoid(acc + bias + hterm[b]); r*hv      -> Chi/Clo
// EPI 3: acc + bias                                     -> Cf
// EPI 4: g = tanh(acc + ag); z*hv + (1-z)*g             -> Chi/Clo
template<int EPI>
__global__ void __launch_bounds__(256, 2) gemm_mma(
    const __nv_bfloat16* __restrict__ Ahi, const __nv_bfloat16* __restrict__ Alo,
    const __nv_bfloat16* __restrict__ Bhi, const __nv_bfloat16* __restrict__ Blo,
    float* __restrict__ Cf,
    __nv_bfloat16* __restrict__ Chi, __nv_bfloat16* __restrict__ Clo,
    const float* __restrict__ bias, const float* __restrict__ hterm,
    const float* __restrict__ h0c,
    const __nv_bfloat16* __restrict__ hvhi, const __nv_bfloat16* __restrict__ hvlo,
    const float* __restrict__ zb, const float* __restrict__ agb)
{
    extern __shared__ char smem_raw[];
    const uint32_t base = smem_u32(smem_raw);
    const int tid = threadIdx.x;
    const int lane = tid & 31;
    const int w = tid >> 5;
    const int wr = w >> 2;          // 0..1 (64 rows)
    const int wc = w & 3;           // 0..3 (32 cols)
    const int bm = blockIdx.y * BM;
    const int bn = blockIdx.x * BN;

    float c[4][4][4];
    #pragma unroll
    for (int i = 0; i < 4; i++)
        #pragma unroll
        for (int j = 0; j < 4; j++)
            #pragma unroll
            for (int e = 0; e < 4; e++) c[i][j][e] = 0.f;

    // per-lane ldmatrix byte offsets within a tile (rows 16B-aligned: ROWB=80)
    const uint32_t a_lm = (wr*64 + ((lane>>3)&1)*8 + (lane&7)) * ROWB + (lane>>4)*16;
    const uint32_t b_lm = (wc*32 + (lane>>4)*8 + (lane&7)) * ROWB + ((lane>>3)&1)*16;

    // copy one super-chunk: 4 tiles x (128 rows x 4 16B-chunks) = 2048 chunks, 256 thr -> 8/thr
    const int crow = tid >> 2;        // 0..63
    const int ccs  = (tid & 3) * 16;  // byte offset of 16B chunk in row
    auto issue = [&](int s) {
        const int kk = s * BK + (ccs >> 1);   // elem col
        const uint32_t sb = base + (s & 1) * SLOT;
        #pragma unroll
        for (int i = 0; i < 2; i++) {
            const int row = crow + i * 64;
            const uint32_t so = row * ROWB + ccs;
            const size_t ga = (size_t)(bm + row) * 512 + kk;
            const size_t gb = (size_t)(bn + row) * 512 + kk;
            cp_async16(sb + A_HI_OFF + so, Ahi + ga);
            cp_async16(sb + A_LO_OFF + so, Alo + ga);
            cp_async16(sb + B_HI_OFF + so, Bhi + gb);
            cp_async16(sb + B_LO_OFF + so, Blo + gb);
        }
    };

    issue(0); cp_commit();

    for (int s = 0; s < NSUP; s++) {
        // pending groups: only {s} (s+1 issued below, after the sync)
        if (s + 1 < NSUP) cp_wait1(); else cp_wait0();
        // NOTE: at s==0 one group pending -> wait1 returns immediately would be wrong;
        // handle explicitly: wait for slot s to be resident.
        // (cp_wait1 allows newest in flight; here only ONE group pending so wait0 semantics needed)
        cp_wait0();
        __syncthreads();                 // all warps done computing slot s-1
        if (s + 1 < NSUP) { issue(s + 1); cp_commit(); }

        const uint32_t sb = base + (s & 1) * SLOT;
        #pragma unroll
        for (int kh = 0; kh < 2; kh++) {
            const uint32_t ko = kh * 32;
            uint32_t ah[4][4], bh[4][2];
            #pragma unroll
            for (int mt = 0; mt < 4; mt++)
                ldmatrix4(ah[mt][0], ah[mt][1], ah[mt][2], ah[mt][3],
                          sb + A_HI_OFF + a_lm + mt * (16*ROWB) + ko);
            #pragma unroll
            for (int np = 0; np < 2; np++) {
                uint32_t r0, r1, r2, r3;
                ldmatrix4(r0, r1, r2, r3, sb + B_HI_OFF + b_lm + np * (16*ROWB) + ko);
                bh[np*2][0] = r0;   bh[np*2][1] = r1;
                bh[np*2+1][0] = r2; bh[np*2+1][1] = r3;
            }
            #pragma unroll
            for (int mt = 0; mt < 4; mt++)
                #pragma unroll
                for (int nt = 0; nt < 4; nt++)
                    mma_bf16(c[mt][nt], ah[mt], bh[nt]);
            {   // hl: Ahi x Blo
                uint32_t bl[4][2];
                #pragma unroll
                for (int np = 0; np < 2; np++) {
                    uint32_t r0, r1, r2, r3;
                    ldmatrix4(r0, r1, r2, r3, sb + B_LO_OFF + b_lm + np * (16*ROWB) + ko);
                    bl[np*2][0] = r0;   bl[np*2][1] = r1;
                    bl[np*2+1][0] = r2; bl[np*2+1][1] = r3;
                }
                #pragma unroll
                for (int mt = 0; mt < 4; mt++)
                    #pragma unroll
                    for (int nt = 0; nt < 4; nt++)
                        mma_bf16(c[mt][nt], ah[mt], bl[nt]);
            }
            {   // lh: Alo x Bhi
                uint32_t al[4][4];
                #pragma unroll
                for (int mt = 0; mt < 4; mt++)
                    ldmatrix4(al[mt][0], al[mt][1], al[mt][2], al[mt][3],
                              sb + A_LO_OFF + a_lm + mt * (16*ROWB) + ko);
                #pragma unroll
                for (int mt = 0; mt < 4; mt++)
                    #pragma unroll
                    for (int nt = 0; nt < 4; nt++)
                        mma_bf16(c[mt][nt], al[mt], bh[nt]);
            }
        }
    }

    // ---- fused epilogue (registers only) ----
    const int rbase = bm + wr * 64;
    const int cbase = bn + wc * 32;
    #pragma unroll
    for (int mt = 0; mt < 4; mt++) {
        #pragma unroll
        for (int er = 0; er < 2; er++) {
            const int gm = rbase + mt*16 + (lane >> 2) + er*8;
            const int bb = gm >> 10;
            #pragma unroll
            for (int nt = 0; nt < 4; nt++) {
                #pragma unroll
                for (int ec = 0; ec < 2; ec++) {
                    const int gn = cbase + nt*8 + (lane & 3)*2 + ec;
                    const size_t idx = (size_t)gm * NN + gn;
                    float v = c[mt][nt][er*2 + ec];
                    if (EPI == 1) {
                        v += bias[gn];
                        if (hterm) v += hterm[bb * NH + gn];
                        Cf[idx] = 1.f / (1.f + __expf(-v));
                    } else if (EPI == 2) {
                        v += bias[gn];
                        if (hterm) v += hterm[bb * NH + gn];
                        float r_ = 1.f / (1.f + __expf(-v));
                        float hv = h0c ? h0c[bb * NH + gn]
                                       : __bfloat162float(hvhi[idx]) + __bfloat162float(hvlo[idx]);
                        float o = r_ * hv;
                        __nv_bfloat16 h, l; split2(o, h, l);
                        Chi[idx] = h; Clo[idx] = l;
                    } else if (EPI == 3) {
                        Cf[idx] = v + (bias ? bias[gn] : 0.f);
                    } else {
                        float g = tanhf(v + agb[idx]);
                        float z = zb[idx];
                        float hv = h0c ? h0c[bb * NH + gn]
                                       : __bfloat162float(hvhi[idx]) + __bfloat162float(hvlo[idx]);
                        float o = z * hv + (1.f - z) * g;
                        __nv_bfloat16 h, l; split2(o, h, l);
                        Chi[idx] = h; Clo[idx] = l;
                    }
                }
            }
        }
    }
}

// ---------------- host ----------------
extern "C" void kernel_launch(void* const* d_in, const int* in_sizes, int n_in,
                              void* d_out, int out_size) {
    const float* input = (const float*)d_in[0];
    const float* hs    = (const float*)d_in[1];
    const float* Wzx   = (const float*)d_in[2];
    const float* bzx   = (const float*)d_in[3];
    const float* Wzh   = (const float*)d_in[4];
    const float* Wrx   = (const float*)d_in[5];
    const float* brx   = (const float*)d_in[6];
    const float* Wrh   = (const float*)d_in[7];
    const float* Wgx   = (const float*)d_in[8];
    const float* bgx   = (const float*)d_in[9];
    const float* Wgh   = (const float*)d_in[10];
    const float* Wout  = (const float*)d_in[11];
    const float* bout  = (const float*)d_in[12];
    float* out = (float*)d_out;

    __nv_bfloat16 *ahi, *alo, *whi, *wlo;
    float *z, *ag, *hz, *hr, *h0c;
    cudaGetSymbolAddress((void**)&ahi, g_act_hi);
    cudaGetSymbolAddress((void**)&alo, g_act_lo);
    cudaGetSymbolAddress((void**)&whi, g_wt_hi);
    cudaGetSymbolAddress((void**)&wlo, g_wt_lo);
    cudaGetSymbolAddress((void**)&z,   g_z);
    cudaGetSymbolAddress((void**)&ag,  g_ag);
    cudaGetSymbolAddress((void**)&hz,  g_hz);
    cudaGetSymbolAddress((void**)&hr,  g_hr);
    cudaGetSymbolAddress((void**)&h0c, g_h0c);

    cudaFuncSetAttribute(gemm_mma<1>, cudaFuncAttributeMaxDynamicSharedMemorySize, SMEM_BYTES);
    cudaFuncSetAttribute(gemm_mma<2>, cudaFuncAttributeMaxDynamicSharedMemorySize, SMEM_BYTES);
    cudaFuncSetAttribute(gemm_mma<3>, cudaFuncAttributeMaxDynamicSharedMemorySize, SMEM_BYTES);
    cudaFuncSetAttribute(gemm_mma<4>, cudaFuncAttributeMaxDynamicSharedMemorySize, SMEM_BYTES);

    // ---- prep ----
    k_split<<<PLANE/4/256, 256>>>((const float4*)input, ahi, alo);
    k_pre<<<dim3(64,2), 512>>>(hs, Wzh, Wrh, hz, hr, h0c);
    k_wprep_all<<<dim3(16,16,13), dim3(32,8)>>>(Wzx, Wzh, Wrx, Wrh, Wgx, Wgh, Wout, whi, wlo);

    dim3 grid(NN / BN, NM / BM);   // (4, 512)
    dim3 blk(256);
    __nv_bfloat16* AH[5]; __nv_bfloat16* AL[5];
    for (int i = 0; i < 5; i++) { AH[i] = ahi + (size_t)i*PLANE; AL[i] = alo + (size_t)i*PLANE; }
    #define WSLOT(s) (whi + (size_t)(s)*WSTRIDE), (wlo + (size_t)(s)*WSTRIDE)

    // ---- layer 0 (h = const h0; x = input, plane 0) ----
    gemm_mma<1><<<grid,blk,SMEM_BYTES>>>(AH[0],AL[0], WSLOT(0),  z,  nullptr,nullptr, bzx,      hz,  nullptr, nullptr,nullptr, nullptr,nullptr);
    gemm_mma<2><<<grid,blk,SMEM_BYTES>>>(AH[0],AL[0], WSLOT(1),  nullptr, AH[1],AL[1], brx,     hr,  h0c,     nullptr,nullptr, nullptr,nullptr);
    gemm_mma<3><<<grid,blk,SMEM_BYTES>>>(AH[0],AL[0], WSLOT(2),  ag, nullptr,nullptr, bgx,      nullptr,nullptr, nullptr,nullptr, nullptr,nullptr);
    gemm_mma<4><<<grid,blk,SMEM_BYTES>>>(AH[1],AL[1], WSLOT(3),  nullptr, AH[2],AL[2], nullptr, nullptr, h0c, nullptr,nullptr, z, ag);
    // ---- layer 1 (x == h == plane 2) ----
    gemm_mma<1><<<grid,blk,SMEM_BYTES>>>(AH[2],AL[2], WSLOT(4),  z,  nullptr,nullptr, bzx+512,  nullptr,nullptr, nullptr,nullptr, nullptr,nullptr);
    gemm_mma<2><<<grid,blk,SMEM_BYTES>>>(AH[2],AL[2], WSLOT(5),  nullptr, AH[1],AL[1], brx+512, nullptr, nullptr, AH[2],AL[2], nullptr,nullptr);
    gemm_mma<3><<<grid,blk,SMEM_BYTES>>>(AH[2],AL[2], WSLOT(6),  ag, nullptr,nullptr, bgx+512,  nullptr,nullptr, nullptr,nullptr, nullptr,nullptr);
    gemm_mma<4><<<grid,blk,SMEM_BYTES>>>(AH[1],AL[1], WSLOT(7),  nullptr, AH[3],AL[3], nullptr, nullptr, nullptr, AH[2],AL[2], z, ag);
    // ---- layer 2 (x == h == plane 3) ----
    gemm_mma<1><<<grid,blk,SMEM_BYTES>>>(AH[3],AL[3], WSLOT(8),  z,  nullptr,nullptr, bzx+1024, nullptr,nullptr, nullptr,nullptr, nullptr,nullptr);
    gemm_mma<2><<<grid,blk,SMEM_BYTES>>>(AH[3],AL[3], WSLOT(9),  nullptr, AH[1],AL[1], brx+1024, nullptr, nullptr, AH[3],AL[3], nullptr,nullptr);
    gemm_mma<3><<<grid,blk,SMEM_BYTES>>>(AH[3],AL[3], WSLOT(10), ag, nullptr,nullptr, bgx+1024, nullptr,nullptr, nullptr,nullptr, nullptr,nullptr);
    gemm_mma<4><<<grid,blk,SMEM_BYTES>>>(AH[1],AL[1], WSLOT(11), nullptr, AH[4],AL[4], nullptr, nullptr, nullptr, AH[3],AL[3], z, ag);
    // ---- output projection ----
    gemm_mma<3><<<grid,blk,SMEM_BYTES>>>(AH[4],AL[4], WSLOT(12), out, nullptr,nullptr, bout,    nullptr,nullptr, nullptr,nullptr, nullptr,nullptr);

    k_tail<<<64, 512>>>(hs, AH[2],AL[2], AH[3],AL[3], out + PLANE);
}